// round 9
// baseline (speedup 1.0000x reference)
#include <cuda_runtime.h>
#include <float.h>

// -------- scratch (no allocations; zero-init; finishers reset) --------
#define MAXS 32768
#define MAXC 65536
__device__ int                g_off     [MAXS + 1]; // exclusive prefix sum + sentinel
__device__ int                g_chunkseg[MAXC];     // chunk -> containing segment
__device__ unsigned long long g_tden[MAXS];         // fixed-point (2^34) Σ e^t
__device__ unsigned long long g_msum[MAXS];         // fixed-point Σ e^m
__device__ unsigned long long g_dot [MAXS];         // fixed-point Σ e^t * m
__device__ unsigned int       g_cnt [MAXS];         // chunks completed per segment
__device__ unsigned long long g_acc;                // fixed-point global Σ ce
__device__ unsigned int       g_done;               // finished segments

#define SCALE     17179869184.0   // 2^34
#define INV_SCALE 0x1p-34f        // exact power-of-two

// ============================================================
// Kernel 1: coalesced prefix-scan of scope[] (single block)
// ============================================================
__global__ void __launch_bounds__(1024)
scan_kernel(const int* __restrict__ scope, int S, int N)
{
    __shared__ int s_w[32];
    const int tid  = threadIdx.x;
    const int lane = tid & 31;
    const int wid  = tid >> 5;

    if (tid == 0) g_off[S] = N;  // sentinel

    if (S == 16384) {
        const int4* s4 = reinterpret_cast<const int4*>(scope);
        int4 v[4];
        #pragma unroll
        for (int k = 0; k < 4; ++k) v[k] = s4[k * 1024 + tid];   // MLP=4, coalesced

        int carry = 0;
        #pragma unroll
        for (int k = 0; k < 4; ++k) {
            const int loc = v[k].x + v[k].y + v[k].z + v[k].w;

            int x = loc;
            #pragma unroll
            for (int off = 1; off < 32; off <<= 1) {
                int y = __shfl_up_sync(0xffffffffu, x, off);
                if (lane >= off) x += y;
            }
            if (lane == 31) s_w[wid] = x;
            __syncthreads();
            if (wid == 0) {
                int w = s_w[lane];
                #pragma unroll
                for (int off = 1; off < 32; off <<= 1) {
                    int y = __shfl_up_sync(0xffffffffu, w, off);
                    if (lane >= off) w += y;
                }
                s_w[lane] = w;
            }
            __syncthreads();

            const int excl = ((wid == 0) ? 0 : s_w[wid - 1]) + (x - loc);
            const int tot  = s_w[31];

            int run = carry + excl;
            int4 o;
            o.x = run; run += v[k].x;
            o.y = run; run += v[k].y;
            o.z = run; run += v[k].z;
            o.w = run; run += v[k].w;
            reinterpret_cast<int4*>(g_off)[k * 1024 + tid] = o;

            carry += tot;
            __syncthreads();
        }
    } else {
        const int per   = (S + 1023) / 1024;
        const int begin = min(tid * per, S);
        const int end   = min(begin + per, S);
        int local = 0;
        for (int i = begin; i < end; ++i) local += scope[i];
        int x = local;
        #pragma unroll
        for (int off = 1; off < 32; off <<= 1) {
            int y = __shfl_up_sync(0xffffffffu, x, off);
            if (lane >= off) x += y;
        }
        if (lane == 31) s_w[wid] = x;
        __syncthreads();
        if (wid == 0) {
            int w = s_w[lane];
            #pragma unroll
            for (int off = 1; off < 32; off <<= 1) {
                int y = __shfl_up_sync(0xffffffffu, w, off);
                if (lane >= off) w += y;
            }
            s_w[lane] = w;
        }
        __syncthreads();
        int run = ((wid == 0) ? 0 : s_w[wid - 1]) + (x - local);
        for (int i = begin; i < end; ++i) { g_off[i] = run; run += scope[i]; }
    }
}

// ============================================================
// Kernel 2: parallel chunk->segment map (1 thread per segment).
// Empty segments (len 0) contribute ce=0: count them done here.
// ============================================================
__global__ void __launch_bounds__(256)
map_kernel(int S)
{
    const int s = blockIdx.x * 256 + threadIdx.x;
    if (s >= S) return;
    const int start = g_off[s];
    const int end   = g_off[s + 1];
    if (start == end) { atomicAdd(&g_done, 1u); return; }  // empty segment
    for (int c = (start + 255) >> 8; (c << 8) < end; ++c)
        g_chunkseg[c] = s;
}

// ============================================================
// Kernel 3: one WARP per 256-element chunk. Streaming pass +
// per-segment last-arriver CE finalization + global last-segment
// output write. No trailing kernel needed.
// ============================================================
__global__ void __launch_bounds__(256)
main_kernel(const float* __restrict__ means,
            const float* __restrict__ targets,
            float* __restrict__ out,
            int N, int S)
{
    const int lane = threadIdx.x & 31;
    const int warp = (blockIdx.x * 256 + threadIdx.x) >> 5;
    const int base = warp * 256;
    if (base >= N) return;

    int s = g_chunkseg[warp];   // 1 load replaces binary search

    const int pos0 = base + lane * 4;
    const int pos1 = base + 128 + lane * 4;

    float e[8], w[8], d[8];
    if (base + 256 <= N) {
        const float4* tp = reinterpret_cast<const float4*>(targets);
        const float4* mp = reinterpret_cast<const float4*>(means);
        const int q = (base >> 2) + lane;
        float4 t0 = tp[q];        float4 t1 = tp[q + 32];
        float4 m0 = mp[q];        float4 m1 = mp[q + 32];
        float tt[8] = {t0.x,t0.y,t0.z,t0.w, t1.x,t1.y,t1.z,t1.w};
        float mm[8] = {m0.x,m0.y,m0.z,m0.w, m1.x,m1.y,m1.z,m1.w};
        #pragma unroll
        for (int j = 0; j < 8; ++j) {
            e[j] = __expf(tt[j]);
            w[j] = __expf(mm[j]);
            d[j] = e[j] * mm[j];
        }
    } else {
        #pragma unroll
        for (int j = 0; j < 8; ++j) {
            int p = (j < 4) ? (pos0 + j) : (pos1 + j - 4);
            float tv = (p < N) ? targets[p] : 0.f;
            float mv = (p < N) ? means[p]   : 0.f;
            e[j] = __expf(tv);
            w[j] = __expf(mv);
            d[j] = e[j] * mv;
        }
    }

    const int last = min(base + 255, N - 1);
    int lower = g_off[s];
    for (;;) {
        const int next = g_off[s + 1];  // sentinel guarantees validity
        float a = 0.f, b = 0.f, c = 0.f;
        #pragma unroll
        for (int j = 0; j < 8; ++j) {
            const int p = (j < 4) ? (pos0 + j) : (pos1 + j - 4);
            if (p >= lower && p < next) { a += e[j]; b += w[j]; c += d[j]; }
        }
        #pragma unroll
        for (int o = 16; o; o >>= 1) {
            a += __shfl_xor_sync(0xffffffffu, a, o);
            b += __shfl_xor_sync(0xffffffffu, b, o);
            c += __shfl_xor_sync(0xffffffffu, c, o);
        }
        if (lane == 0) {
            atomicAdd(&g_tden[s], (unsigned long long)__double2ll_rn((double)a * SCALE));
            atomicAdd(&g_msum[s], (unsigned long long)__double2ll_rn((double)b * SCALE));
            atomicAdd(&g_dot [s], (unsigned long long)__double2ll_rn((double)c * SCALE));
            __threadfence();   // release: sums visible before count

            // number of chunks overlapping [lower, next)
            const unsigned int nchunks =
                (unsigned int)(((next - 1) >> 8) - (lower >> 8) + 1);
            unsigned int old = atomicAdd(&g_cnt[s], 1u);
            if (old == nchunks - 1u) {
                __threadfence();   // acquire: read final sums
                long long tdq = (long long)__ldcg(&g_tden[s]);
                float td = __ll2float_rn(tdq);                                  // scale cancels
                float ms = __ll2float_rn((long long)__ldcg(&g_msum[s])) * INV_SCALE;
                float dt = __ll2float_rn((long long)__ldcg(&g_dot [s]));
                float ce = (tdq > 0) ? (dt / td - __logf(ms)) : 0.f;

                // reset this segment's scratch for the next graph replay
                g_tden[s] = 0ull; g_msum[s] = 0ull; g_dot[s] = 0ull; g_cnt[s] = 0u;

                atomicAdd(&g_acc, (unsigned long long)__double2ll_rn((double)ce * SCALE));
                __threadfence();
                unsigned int p = atomicAdd(&g_done, 1u);
                if (p == (unsigned int)(S - 1)) {
                    unsigned long long tot = atomicAdd(&g_acc, 0ull);  // ordered read
                    double sum = (double)(long long)tot / SCALE;
                    out[0] = (float)(-sum / (double)S);
                    g_acc  = 0ull;   // reset for next replay
                    g_done = 0u;
                    __threadfence();
                }
            }
        }
        __syncwarp();
        if (next > last) break;
        lower = next;
        ++s;
    }
}

// ============================================================
extern "C" void kernel_launch(void* const* d_in, const int* in_sizes, int n_in,
                              void* d_out, int out_size)
{
    const float* means   = (const float*)d_in[0];
    const int*   scope   = (const int*)  d_in[1];
    const float* targets = (const float*)d_in[2];
    const int N = in_sizes[0];
    const int S = in_sizes[1];

    scan_kernel<<<1, 1024>>>(scope, S, N);
    map_kernel<<<(S + 255) / 256, 256>>>(S);

    const int nWarps  = (N + 255) / 256;
    const int nBlocks = (nWarps + 7) / 8;
    main_kernel<<<nBlocks, 256>>>(means, targets, (float*)d_out, N, S);
}